// round 12
// baseline (speedup 1.0000x reference)
#include <cuda_runtime.h>
#include <cuda_fp16.h>

// Problem constants
#define Bb    4
#define Tt    16
#define Hh    64
#define Ww    64
#define Cc    256
#define NCLS  512
#define TAPS  27
#define NK    (NCLS * TAPS)           // 13824
#define WCHUNK 32
#define WOFF_BYTES  (TAPS * Cc * 2)   // 13824 B per class in main table
#define CWOFF_BYTES (9 * Cc * 2)      // 4608 B per class in combined tables

// Transposed fp16 weight table: [class][tap][channel]
__device__ __align__(16) __half g_wt[NK * Cc];
// Temporal-edge combined tables: [class][dh*3+dw][channel]
__device__ __align__(16) __half g_wc01 [NCLS * 9 * Cc];
__device__ __align__(16) __half g_wc012[NCLS * 9 * Cc];

// ---------------------------------------------------------------------------
// Kernel A1: tiled 2D transpose, 256 x 13824 fp32 -> 13824 x 256 fp16.
// ---------------------------------------------------------------------------
__global__ void __launch_bounds__(256) wt_transpose_kernel(const float* __restrict__ w)
{
    __shared__ float s[32][33];
    const int nk0  = blockIdx.x * 32;
    const int c0   = blockIdx.y * 32;
    const int lane = threadIdx.x & 31;
    const int wrp  = threadIdx.x >> 5;

    #pragma unroll
    for (int r = 0; r < 4; r++) {
        int c = wrp * 4 + r;
        s[c][lane] = w[(size_t)(c0 + c) * NK + nk0 + lane];
    }
    __syncthreads();
    #pragma unroll
    for (int r = 0; r < 4; r++) {
        int nkr = wrp * 4 + r;
        g_wt[(size_t)(nk0 + nkr) * Cc + c0 + lane] = __float2half_rn(s[lane][nkr]);
    }
}

// ---------------------------------------------------------------------------
// Kernel A2: build combined temporal-edge tables from g_wt.
// ---------------------------------------------------------------------------
__global__ void __launch_bounds__(256) wt_combine_kernel()
{
    const int idx = blockIdx.x * 256 + threadIdx.x;   // over NCLS*9*128
    const int c2  = idx & 127;
    const int jt  = (idx >> 7) % 9;
    const int n   = idx / (9 * 128);

    const __half2* wt2 = reinterpret_cast<const __half2*>(g_wt);
    __half2 h0 = wt2[(n * 27 + jt)      * 128 + c2];
    __half2 h1 = wt2[(n * 27 + 9 + jt)  * 128 + c2];
    __half2 h2 = wt2[(n * 27 + 18 + jt) * 128 + c2];
    float2 f0 = __half22float2(h0), f1 = __half22float2(h1), f2 = __half22float2(h2);
    float sx01 = f0.x + f1.x, sy01 = f0.y + f1.y;
    reinterpret_cast<__half2*>(g_wc01)[(n * 9 + jt) * 128 + c2]  = __floats2half2_rn(sx01, sy01);
    reinterpret_cast<__half2*>(g_wc012)[(n * 9 + jt) * 128 + c2] = __floats2half2_rn(sx01 + f2.x, sy01 + f2.y);
}

// accumulate one fp16x8 pair-sum group into two float4 accumulators
#define ACC_PAIR(A0, A1, U0, U1)                                                                      \
    do {                                                                                              \
        __half2 _s0 = __hadd2(*reinterpret_cast<__half2*>(&(U0).x), *reinterpret_cast<__half2*>(&(U1).x)); \
        __half2 _s1 = __hadd2(*reinterpret_cast<__half2*>(&(U0).y), *reinterpret_cast<__half2*>(&(U1).y)); \
        __half2 _s2 = __hadd2(*reinterpret_cast<__half2*>(&(U0).z), *reinterpret_cast<__half2*>(&(U1).z)); \
        __half2 _s3 = __hadd2(*reinterpret_cast<__half2*>(&(U0).w), *reinterpret_cast<__half2*>(&(U1).w)); \
        float2 _f;                                                                                    \
        _f = __half22float2(_s0); (A0).x += _f.x; (A0).y += _f.y;                                     \
        _f = __half22float2(_s1); (A0).z += _f.x; (A0).w += _f.y;                                     \
        _f = __half22float2(_s2); (A1).x += _f.x; (A1).y += _f.y;                                     \
        _f = __half22float2(_s3); (A1).z += _f.x; (A1).w += _f.y;                                     \
    } while (0)

#define ACC_ONE(A0, A1, U)                                                     \
    do {                                                                       \
        float2 _f;                                                             \
        _f = __half22float2(*reinterpret_cast<__half2*>(&(U).x)); (A0).x += _f.x; (A0).y += _f.y; \
        _f = __half22float2(*reinterpret_cast<__half2*>(&(U).y)); (A0).z += _f.x; (A0).w += _f.y; \
        _f = __half22float2(*reinterpret_cast<__half2*>(&(U).z)); (A1).x += _f.x; (A1).y += _f.y; \
        _f = __half22float2(*reinterpret_cast<__half2*>(&(U).w)); (A1).z += _f.x; (A1).w += _f.y; \
    } while (0)

// ---------------------------------------------------------------------------
// Kernel B: gather-accumulate, 2 positions per warp interleaved @ occ 3.
// R12 change: R10/R11 ran 1 position/warp/pass at the 64-reg cap (compiler
// hit exactly 64 -> register-starved pipelining; L1 pipe 80%, 20% idle at
// pass heads/tails). Interleaving 2 positions doubles independent load
// streams per warp so one position's FADD tail covers the other's
// LDS->shuffle->load head. occ-3 (84 regs); occupancy proven irrelevant.
// ---------------------------------------------------------------------------
__global__ void __launch_bounds__(256, 3) onehot_conv_kernel(
    const int*   __restrict__ indices,
    const float* __restrict__ bias,
    float*       __restrict__ out)
{
    __shared__ __align__(16) uint4 s_stage[WCHUNK * 32];  // fp16 stage, 16KB
    __shared__ int s_off[9 * 34];                         // raw classes, halo'd in w

    const int bx   = blockIdx.x;
    const int wblk = bx & 1;
    const int h    = (bx >> 1) & 63;
    const int t    = (bx >> 7) & 15;
    const int b    = bx >> 11;
    const int w0   = wblk * WCHUNK;
    const int tid  = threadIdx.x;

    // Halo of classes: 9 (dt,dh) rows x 34 w, edge-clamped.
    for (int i = tid; i < 9 * 34; i += 256) {
        int r  = i / 34, j = i % 34;
        int dt = r / 3,  dh = r % 3;
        int st = t + dt - 2; if (st < 0) st = 0;
        int sh = h + dh - 1; if (sh < 0) sh = 0; if (sh > Hh - 1) sh = Hh - 1;
        int gw = w0 + j - 1; if (gw < 0) gw = 0; if (gw > Ww - 1) gw = Ww - 1;
        s_off[i] = indices[((b * Tt + st) * Hh + sh) * Ww + gw];
    }
    __syncthreads();

    const int warp = tid >> 5;
    const int lane = tid & 31;
    const int kl   = lane < 27 ? lane : 26;     // lane -> tap (guarded)
    const int rIdx = (kl / 3) * 34 + (kl % 3);  // row part of s_off index

    const char* baseW  = reinterpret_cast<const char*>(g_wt)    + lane * 16;
    const char* baseC1 = reinterpret_cast<const char*>(g_wc01)  + lane * 16;
    const char* baseC2 = reinterpret_cast<const char*>(g_wc012) + lane * 16;

    const float4 bz0 = *reinterpret_cast<const float4*>(bias + 8 * lane);
    const float4 bz1 = *reinterpret_cast<const float4*>(bias + 8 * lane + 4);

    if (t >= 2) {
        // 2 passes x 2 interleaved positions per warp.
        #pragma unroll 1
        for (int p = 0; p < 2; p++) {
            const int wA = p * 16 + warp;       // position A
            const int wB = wA + 8;              // position B
            const int moA = s_off[rIdx + wA] * WOFF_BYTES;
            const int moB = s_off[rIdx + wB] * WOFF_BYTES;

            float4 a0 = bz0, a1 = bz1;          // acc for A
            float4 c0 = bz0, c1 = bz1;          // acc for B

            #pragma unroll
            for (int k = 0; k < 26; k += 2) {
                const int oA0 = __shfl_sync(0xffffffffu, moA, k);
                const int oA1 = __shfl_sync(0xffffffffu, moA, k + 1);
                const int oB0 = __shfl_sync(0xffffffffu, moB, k);
                const int oB1 = __shfl_sync(0xffffffffu, moB, k + 1);
                uint4 uA0 = *reinterpret_cast<const uint4*>(baseW + oA0 + k * 512);
                uint4 uA1 = *reinterpret_cast<const uint4*>(baseW + oA1 + (k + 1) * 512);
                uint4 uB0 = *reinterpret_cast<const uint4*>(baseW + oB0 + k * 512);
                uint4 uB1 = *reinterpret_cast<const uint4*>(baseW + oB1 + (k + 1) * 512);
                ACC_PAIR(a0, a1, uA0, uA1);
                ACC_PAIR(c0, c1, uB0, uB1);
            }
            {
                const int oA = __shfl_sync(0xffffffffu, moA, 26);
                const int oB = __shfl_sync(0xffffffffu, moB, 26);
                uint4 uA = *reinterpret_cast<const uint4*>(baseW + oA + 26 * 512);
                uint4 uB = *reinterpret_cast<const uint4*>(baseW + oB + 26 * 512);
                ACC_ONE(a0, a1, uA);
                ACC_ONE(c0, c1, uB);
            }

            // Pack + swizzled STS for both positions.
            __half2 h0, h1, h2, h3; uint4 pk;
            h0 = __floats2half2_rn(a0.x, a0.y); h1 = __floats2half2_rn(a0.z, a0.w);
            h2 = __floats2half2_rn(a1.x, a1.y); h3 = __floats2half2_rn(a1.z, a1.w);
            pk.x = *reinterpret_cast<unsigned*>(&h0); pk.y = *reinterpret_cast<unsigned*>(&h1);
            pk.z = *reinterpret_cast<unsigned*>(&h2); pk.w = *reinterpret_cast<unsigned*>(&h3);
            s_stage[wA * 32 + (lane ^ (wA & 31))] = pk;
            h0 = __floats2half2_rn(c0.x, c0.y); h1 = __floats2half2_rn(c0.z, c0.w);
            h2 = __floats2half2_rn(c1.x, c1.y); h3 = __floats2half2_rn(c1.z, c1.w);
            pk.x = *reinterpret_cast<unsigned*>(&h0); pk.y = *reinterpret_cast<unsigned*>(&h1);
            pk.z = *reinterpret_cast<unsigned*>(&h2); pk.w = *reinterpret_cast<unsigned*>(&h3);
            s_stage[wB * 32 + (lane ^ (wB & 31))] = pk;
        }
    } else {
        // Temporal-edge blocks (t==0 / t==1): 1/8 of blocks, keep simple
        // (sequential positions, 4 passes).
        #pragma unroll 1
        for (int p = 0; p < 4; p++) {
            const int w_l = p * 8 + warp;
            const int cls = s_off[rIdx + w_l];
            const int moW = cls * WOFF_BYTES;
            const int moC = cls * CWOFF_BYTES;

            float4 a0 = bz0, a1 = bz1;

            if (t == 1) {
                #pragma unroll
                for (int j = 0; j < 9; j++) {
                    const int oc = __shfl_sync(0xffffffffu, moC, j);
                    const int ow = __shfl_sync(0xffffffffu, moW, 18 + j);
                    uint4 u0 = *reinterpret_cast<const uint4*>(baseC1 + oc + j * 512);
                    uint4 u1 = *reinterpret_cast<const uint4*>(baseW + ow + (18 + j) * 512);
                    ACC_PAIR(a0, a1, u0, u1);
                }
            } else {
                #pragma unroll
                for (int j = 0; j < 8; j += 2) {
                    const int o0 = __shfl_sync(0xffffffffu, moC, j);
                    const int o1 = __shfl_sync(0xffffffffu, moC, j + 1);
                    uint4 u0 = *reinterpret_cast<const uint4*>(baseC2 + o0 + j * 512);
                    uint4 u1 = *reinterpret_cast<const uint4*>(baseC2 + o1 + (j + 1) * 512);
                    ACC_PAIR(a0, a1, u0, u1);
                }
                const int o = __shfl_sync(0xffffffffu, moC, 8);
                uint4 u = *reinterpret_cast<const uint4*>(baseC2 + o + 8 * 512);
                ACC_ONE(a0, a1, u);
            }

            __half2 h0 = __floats2half2_rn(a0.x, a0.y);
            __half2 h1 = __floats2half2_rn(a0.z, a0.w);
            __half2 h2 = __floats2half2_rn(a1.x, a1.y);
            __half2 h3 = __floats2half2_rn(a1.z, a1.w);
            uint4 pk;
            pk.x = *reinterpret_cast<unsigned*>(&h0);
            pk.y = *reinterpret_cast<unsigned*>(&h1);
            pk.z = *reinterpret_cast<unsigned*>(&h2);
            pk.w = *reinterpret_cast<unsigned*>(&h3);
            s_stage[w_l * 32 + (lane ^ (w_l & 31))] = pk;
        }
    }
    __syncthreads();

    // Read-back: logical unit uu (8 channels) at phys uu^(lane&31); lane = w.
    const size_t THW   = (size_t)Tt * Hh * Ww;
    const size_t obase = (size_t)b * Cc * THW + (size_t)t * (Hh * Ww) + (size_t)h * Ww + w0;
    #pragma unroll
    for (int uu = warp; uu < 32; uu += 8) {
        uint4 pk = s_stage[lane * 32 + (uu ^ lane)];
        float2 f0 = __half22float2(*reinterpret_cast<__half2*>(&pk.x));
        float2 f1 = __half22float2(*reinterpret_cast<__half2*>(&pk.y));
        float2 f2 = __half22float2(*reinterpret_cast<__half2*>(&pk.z));
        float2 f3 = __half22float2(*reinterpret_cast<__half2*>(&pk.w));
        const int c = uu * 8;
        out[obase + (size_t)(c + 0) * THW + lane] = f0.x;
        out[obase + (size_t)(c + 1) * THW + lane] = f0.y;
        out[obase + (size_t)(c + 2) * THW + lane] = f1.x;
        out[obase + (size_t)(c + 3) * THW + lane] = f1.y;
        out[obase + (size_t)(c + 4) * THW + lane] = f2.x;
        out[obase + (size_t)(c + 5) * THW + lane] = f2.y;
        out[obase + (size_t)(c + 6) * THW + lane] = f3.x;
        out[obase + (size_t)(c + 7) * THW + lane] = f3.y;
    }
}

// ---------------------------------------------------------------------------
extern "C" void kernel_launch(void* const* d_in, const int* in_sizes, int n_in,
                              void* d_out, int out_size)
{
    const int*   indices = (const int*)  d_in[0];
    const float* weight  = (const float*)d_in[1];
    const float* bias    = (const float*)d_in[2];
    float*       out     = (float*)d_out;

    dim3 tgrid(NK / 32, Cc / 32);                  // (432, 8)
    wt_transpose_kernel<<<tgrid, 256>>>(weight);
    wt_combine_kernel<<<NCLS * 9 * 128 / 256, 256>>>();

    const int grid = Bb * Tt * Hh * (Ww / WCHUNK); // 8192
    onehot_conv_kernel<<<grid, 256>>>(indices, bias, out);
}

// round 14
// speedup vs baseline: 1.0159x; 1.0159x over previous
#include <cuda_runtime.h>
#include <cuda_fp16.h>

// Problem constants
#define Bb    4
#define Tt    16
#define Hh    64
#define Ww    64
#define Cc    256
#define NCLS  512
#define TAPS  27
#define NK    (NCLS * TAPS)           // 13824
#define WCHUNK 32
#define WOFF_BYTES  (TAPS * Cc * 2)   // 13824 B per class in main table
#define CWOFF_BYTES (9 * Cc * 2)      // 4608 B per class in combined tables

// Transposed fp16 weight table: [class][tap][channel]
__device__ __align__(16) __half g_wt[NK * Cc];
// Temporal-edge combined tables: [class][dh*3+dw][channel]
__device__ __align__(16) __half g_wc01 [NCLS * 9 * Cc];
__device__ __align__(16) __half g_wc012[NCLS * 9 * Cc];

// ---------------------------------------------------------------------------
// Kernel A1: tiled 2D transpose, 256 x 13824 fp32 -> 13824 x 256 fp16.
// Vectorized: 1 LDG.128 per thread (256 threads), 1 STG.128 per thread for
// the 128 writer threads. R13 bug fixed: write phase has only 32nk x 4units
// = 128 units, so it is guarded to tid < 128 (R13 let all 256 threads write,
// running nkl to 63 -> OOB on g_wt and the smem tile).
// ---------------------------------------------------------------------------
__global__ void __launch_bounds__(256) wt_transpose_kernel(const float* __restrict__ w)
{
    __shared__ float s[32 * 33];
    const int nk0 = blockIdx.x * 32;
    const int c0  = blockIdx.y * 32;
    const int tid = threadIdx.x;

    // Load: thread -> (c_local = tid/8, 4 nk at (tid&7)*4). One LDG.128.
    {
        const int cl = tid >> 3;          // 0..31
        const int k4 = (tid & 7) * 4;     // 0..28
        float4 v = *reinterpret_cast<const float4*>(w + (size_t)(c0 + cl) * NK + nk0 + k4);
        s[cl * 33 + k4 + 0] = v.x;
        s[cl * 33 + k4 + 1] = v.y;
        s[cl * 33 + k4 + 2] = v.z;
        s[cl * 33 + k4 + 3] = v.w;
    }
    __syncthreads();

    // Write: 128 units (32 nk x 4 c-groups of 8). Threads 0..127 only.
    if (tid < 128) {
        const int nkl = tid >> 2;         // 0..31
        const int c8  = (tid & 3) * 8;    // 0..24
        __half2 h0 = __floats2half2_rn(s[(c8+0)*33 + nkl], s[(c8+1)*33 + nkl]);
        __half2 h1 = __floats2half2_rn(s[(c8+2)*33 + nkl], s[(c8+3)*33 + nkl]);
        __half2 h2 = __floats2half2_rn(s[(c8+4)*33 + nkl], s[(c8+5)*33 + nkl]);
        __half2 h3 = __floats2half2_rn(s[(c8+6)*33 + nkl], s[(c8+7)*33 + nkl]);
        uint4 pk;
        pk.x = *reinterpret_cast<unsigned*>(&h0);
        pk.y = *reinterpret_cast<unsigned*>(&h1);
        pk.z = *reinterpret_cast<unsigned*>(&h2);
        pk.w = *reinterpret_cast<unsigned*>(&h3);
        *reinterpret_cast<uint4*>(&g_wt[(size_t)(nk0 + nkl) * Cc + c0 + c8]) = pk;
    }
}

// ---------------------------------------------------------------------------
// Kernel A2: build combined temporal-edge tables from g_wt.
// ---------------------------------------------------------------------------
__global__ void __launch_bounds__(256) wt_combine_kernel()
{
    const int idx = blockIdx.x * 256 + threadIdx.x;   // over NCLS*9*128
    const int c2  = idx & 127;
    const int jt  = (idx >> 7) % 9;
    const int n   = idx / (9 * 128);

    const __half2* wt2 = reinterpret_cast<const __half2*>(g_wt);
    __half2 h0 = wt2[(n * 27 + jt)      * 128 + c2];
    __half2 h1 = wt2[(n * 27 + 9 + jt)  * 128 + c2];
    __half2 h2 = wt2[(n * 27 + 18 + jt) * 128 + c2];
    float2 f0 = __half22float2(h0), f1 = __half22float2(h1), f2 = __half22float2(h2);
    float sx01 = f0.x + f1.x, sy01 = f0.y + f1.y;
    reinterpret_cast<__half2*>(g_wc01)[(n * 9 + jt) * 128 + c2]  = __floats2half2_rn(sx01, sy01);
    reinterpret_cast<__half2*>(g_wc012)[(n * 9 + jt) * 128 + c2] = __floats2half2_rn(sx01 + f2.x, sy01 + f2.y);
}

// ---------------------------------------------------------------------------
// Kernel B: gather-accumulate — EXACT R11 config (best main: 175.0us).
// LDG.128, pairwise HADD2, fp16 smem staging, full pass unroll @ occ 4,
// temporal-edge combined taps. At the l1tex steady-state service ceiling.
// ---------------------------------------------------------------------------
__global__ void __launch_bounds__(256, 4) onehot_conv_kernel(
    const int*   __restrict__ indices,
    const float* __restrict__ bias,
    float*       __restrict__ out)
{
    __shared__ __align__(16) uint4 s_stage[WCHUNK * 32];  // fp16 stage, 16KB
    __shared__ int s_off[9 * 34];                         // raw classes, halo'd in w

    const int bx   = blockIdx.x;
    const int wblk = bx & 1;
    const int h    = (bx >> 1) & 63;
    const int t    = (bx >> 7) & 15;
    const int b    = bx >> 11;
    const int w0   = wblk * WCHUNK;
    const int tid  = threadIdx.x;

    for (int i = tid; i < 9 * 34; i += 256) {
        int r  = i / 34, j = i % 34;
        int dt = r / 3,  dh = r % 3;
        int st = t + dt - 2; if (st < 0) st = 0;
        int sh = h + dh - 1; if (sh < 0) sh = 0; if (sh > Hh - 1) sh = Hh - 1;
        int gw = w0 + j - 1; if (gw < 0) gw = 0; if (gw > Ww - 1) gw = Ww - 1;
        s_off[i] = indices[((b * Tt + st) * Hh + sh) * Ww + gw];
    }
    __syncthreads();

    const int warp = tid >> 5;
    const int lane = tid & 31;
    const int kl   = lane < 27 ? lane : 26;
    const int rIdx = (kl / 3) * 34 + (kl % 3);

    const char* baseW  = reinterpret_cast<const char*>(g_wt)    + lane * 16;
    const char* baseC1 = reinterpret_cast<const char*>(g_wc01)  + lane * 16;
    const char* baseC2 = reinterpret_cast<const char*>(g_wc012) + lane * 16;

    const float4 bz0 = *reinterpret_cast<const float4*>(bias + 8 * lane);
    const float4 bz1 = *reinterpret_cast<const float4*>(bias + 8 * lane + 4);

    #pragma unroll
    for (int p = 0; p < 4; p++) {
        const int w_l = p * 8 + warp;
        const int cls = s_off[rIdx + w_l];
        const int moW = cls * WOFF_BYTES;
        const int moC = cls * CWOFF_BYTES;

        float4 a0 = bz0, a1 = bz1;

        if (t >= 2) {
            #pragma unroll
            for (int k = 0; k < 26; k += 2) {
                const int o0 = __shfl_sync(0xffffffffu, moW, k);
                const int o1 = __shfl_sync(0xffffffffu, moW, k + 1);
                uint4 u0 = *reinterpret_cast<const uint4*>(baseW + o0 + k * 512);
                uint4 u1 = *reinterpret_cast<const uint4*>(baseW + o1 + (k + 1) * 512);
                __half2 s0 = __hadd2(*reinterpret_cast<__half2*>(&u0.x), *reinterpret_cast<__half2*>(&u1.x));
                __half2 s1 = __hadd2(*reinterpret_cast<__half2*>(&u0.y), *reinterpret_cast<__half2*>(&u1.y));
                __half2 s2 = __hadd2(*reinterpret_cast<__half2*>(&u0.z), *reinterpret_cast<__half2*>(&u1.z));
                __half2 s3 = __hadd2(*reinterpret_cast<__half2*>(&u0.w), *reinterpret_cast<__half2*>(&u1.w));
                float2 f;
                f = __half22float2(s0); a0.x += f.x; a0.y += f.y;
                f = __half22float2(s1); a0.z += f.x; a0.w += f.y;
                f = __half22float2(s2); a1.x += f.x; a1.y += f.y;
                f = __half22float2(s3); a1.z += f.x; a1.w += f.y;
            }
            const int o = __shfl_sync(0xffffffffu, moW, 26);
            uint4 u = *reinterpret_cast<const uint4*>(baseW + o + 26 * 512);
            float2 f;
            f = __half22float2(*reinterpret_cast<__half2*>(&u.x)); a0.x += f.x; a0.y += f.y;
            f = __half22float2(*reinterpret_cast<__half2*>(&u.y)); a0.z += f.x; a0.w += f.y;
            f = __half22float2(*reinterpret_cast<__half2*>(&u.z)); a1.x += f.x; a1.y += f.y;
            f = __half22float2(*reinterpret_cast<__half2*>(&u.w)); a1.z += f.x; a1.w += f.y;
        } else if (t == 1) {
            #pragma unroll
            for (int j = 0; j < 9; j++) {
                const int oc = __shfl_sync(0xffffffffu, moC, j);
                const int ow = __shfl_sync(0xffffffffu, moW, 18 + j);
                uint4 u0 = *reinterpret_cast<const uint4*>(baseC1 + oc + j * 512);
                uint4 u1 = *reinterpret_cast<const uint4*>(baseW + ow + (18 + j) * 512);
                __half2 s0 = __hadd2(*reinterpret_cast<__half2*>(&u0.x), *reinterpret_cast<__half2*>(&u1.x));
                __half2 s1 = __hadd2(*reinterpret_cast<__half2*>(&u0.y), *reinterpret_cast<__half2*>(&u1.y));
                __half2 s2 = __hadd2(*reinterpret_cast<__half2*>(&u0.z), *reinterpret_cast<__half2*>(&u1.z));
                __half2 s3 = __hadd2(*reinterpret_cast<__half2*>(&u0.w), *reinterpret_cast<__half2*>(&u1.w));
                float2 f;
                f = __half22float2(s0); a0.x += f.x; a0.y += f.y;
                f = __half22float2(s1); a0.z += f.x; a0.w += f.y;
                f = __half22float2(s2); a1.x += f.x; a1.y += f.y;
                f = __half22float2(s3); a1.z += f.x; a1.w += f.y;
            }
        } else {
            #pragma unroll
            for (int j = 0; j < 8; j += 2) {
                const int o0 = __shfl_sync(0xffffffffu, moC, j);
                const int o1 = __shfl_sync(0xffffffffu, moC, j + 1);
                uint4 u0 = *reinterpret_cast<const uint4*>(baseC2 + o0 + j * 512);
                uint4 u1 = *reinterpret_cast<const uint4*>(baseC2 + o1 + (j + 1) * 512);
                __half2 s0 = __hadd2(*reinterpret_cast<__half2*>(&u0.x), *reinterpret_cast<__half2*>(&u1.x));
                __half2 s1 = __hadd2(*reinterpret_cast<__half2*>(&u0.y), *reinterpret_cast<__half2*>(&u1.y));
                __half2 s2 = __hadd2(*reinterpret_cast<__half2*>(&u0.z), *reinterpret_cast<__half2*>(&u1.z));
                __half2 s3 = __hadd2(*reinterpret_cast<__half2*>(&u0.w), *reinterpret_cast<__half2*>(&u1.w));
                float2 f;
                f = __half22float2(s0); a0.x += f.x; a0.y += f.y;
                f = __half22float2(s1); a0.z += f.x; a0.w += f.y;
                f = __half22float2(s2); a1.x += f.x; a1.y += f.y;
                f = __half22float2(s3); a1.z += f.x; a1.w += f.y;
            }
            const int o = __shfl_sync(0xffffffffu, moC, 8);
            uint4 u = *reinterpret_cast<const uint4*>(baseC2 + o + 8 * 512);
            float2 f;
            f = __half22float2(*reinterpret_cast<__half2*>(&u.x)); a0.x += f.x; a0.y += f.y;
            f = __half22float2(*reinterpret_cast<__half2*>(&u.y)); a0.z += f.x; a0.w += f.y;
            f = __half22float2(*reinterpret_cast<__half2*>(&u.z)); a1.x += f.x; a1.y += f.y;
            f = __half22float2(*reinterpret_cast<__half2*>(&u.w)); a1.z += f.x; a1.w += f.y;
        }

        __half2 h0 = __floats2half2_rn(a0.x, a0.y);
        __half2 h1 = __floats2half2_rn(a0.z, a0.w);
        __half2 h2 = __floats2half2_rn(a1.x, a1.y);
        __half2 h3 = __floats2half2_rn(a1.z, a1.w);
        uint4 pk;
        pk.x = *reinterpret_cast<unsigned*>(&h0);
        pk.y = *reinterpret_cast<unsigned*>(&h1);
        pk.z = *reinterpret_cast<unsigned*>(&h2);
        pk.w = *reinterpret_cast<unsigned*>(&h3);
        s_stage[w_l * 32 + (lane ^ (w_l & 31))] = pk;
    }
    __syncthreads();

    const size_t THW   = (size_t)Tt * Hh * Ww;
    const size_t obase = (size_t)b * Cc * THW + (size_t)t * (Hh * Ww) + (size_t)h * Ww + w0;
    #pragma unroll
    for (int uu = warp; uu < 32; uu += 8) {
        uint4 pk = s_stage[lane * 32 + (uu ^ lane)];
        float2 f0 = __half22float2(*reinterpret_cast<__half2*>(&pk.x));
        float2 f1 = __half22float2(*reinterpret_cast<__half2*>(&pk.y));
        float2 f2 = __half22float2(*reinterpret_cast<__half2*>(&pk.z));
        float2 f3 = __half22float2(*reinterpret_cast<__half2*>(&pk.w));
        const int c = uu * 8;
        out[obase + (size_t)(c + 0) * THW + lane] = f0.x;
        out[obase + (size_t)(c + 1) * THW + lane] = f0.y;
        out[obase + (size_t)(c + 2) * THW + lane] = f1.x;
        out[obase + (size_t)(c + 3) * THW + lane] = f1.y;
        out[obase + (size_t)(c + 4) * THW + lane] = f2.x;
        out[obase + (size_t)(c + 5) * THW + lane] = f2.y;
        out[obase + (size_t)(c + 6) * THW + lane] = f3.x;
        out[obase + (size_t)(c + 7) * THW + lane] = f3.y;
    }
}

// ---------------------------------------------------------------------------
extern "C" void kernel_launch(void* const* d_in, const int* in_sizes, int n_in,
                              void* d_out, int out_size)
{
    const int*   indices = (const int*)  d_in[0];
    const float* weight  = (const float*)d_in[1];
    const float* bias    = (const float*)d_in[2];
    float*       out     = (float*)d_out;

    dim3 tgrid(NK / 32, Cc / 32);                  // (432, 8)
    wt_transpose_kernel<<<tgrid, 256>>>(weight);
    wt_combine_kernel<<<NCLS * 9 * 128 / 256, 256>>>();

    const int grid = Bb * Tt * Hh * (Ww / WCHUNK); // 8192
    onehot_conv_kernel<<<grid, 256>>>(indices, bias, out);
}

// round 15
// speedup vs baseline: 1.0201x; 1.0041x over previous
#include <cuda_runtime.h>
#include <cuda_fp16.h>

// Problem constants
#define Bb    4
#define Tt    16
#define Hh    64
#define Ww    64
#define Cc    256
#define NCLS  512
#define TAPS  27
#define NK    (NCLS * TAPS)           // 13824
#define WCHUNK 32
#define WOFF_BYTES  (TAPS * Cc * 2)   // 13824 B per class in main table
#define CWOFF_BYTES (9 * Cc * 2)      // 4608 B per class in combined tables

// Transposed fp16 weight table: [class][tap][channel]
__device__ __align__(16) __half g_wt[NK * Cc];
// Temporal-edge combined tables: [class][dh*3+dw][channel]
__device__ __align__(16) __half g_wc01 [NCLS * 9 * Cc];
__device__ __align__(16) __half g_wc012[NCLS * 9 * Cc];

// ---------------------------------------------------------------------------
// Kernel A1: tiled 2D transpose, 256 x 13824 fp32 -> 13824 x 256 fp16.
// R15: MLP=4 — each block covers 128nk x 32c as 4 sub-tiles whose 4
// independent LDG.128 are issued up-front into registers (R14 had 1 LDG
// per thread -> latency-bound at ~620 cyc/block, 7.9us @ issue 22%).
// Then one sync and 2 STG.128 per thread. grid = (NK/128, Cc/32) = (108,8).
// ---------------------------------------------------------------------------
__global__ void __launch_bounds__(256) wt_transpose_kernel(const float* __restrict__ w)
{
    __shared__ float s[4][32 * 33];
    const int nk0 = blockIdx.x * 128;
    const int c0  = blockIdx.y * 32;
    const int tid = threadIdx.x;

    // Load: 4 independent LDG.128 per thread (one per sub-tile).
    const int cl = tid >> 3;          // 0..31
    const int k4 = (tid & 7) * 4;     // 0..28
    const float* rowp = w + (size_t)(c0 + cl) * NK + nk0 + k4;
    float4 v0 = *reinterpret_cast<const float4*>(rowp);
    float4 v1 = *reinterpret_cast<const float4*>(rowp + 32);
    float4 v2 = *reinterpret_cast<const float4*>(rowp + 64);
    float4 v3 = *reinterpret_cast<const float4*>(rowp + 96);

    s[0][cl * 33 + k4 + 0] = v0.x; s[0][cl * 33 + k4 + 1] = v0.y;
    s[0][cl * 33 + k4 + 2] = v0.z; s[0][cl * 33 + k4 + 3] = v0.w;
    s[1][cl * 33 + k4 + 0] = v1.x; s[1][cl * 33 + k4 + 1] = v1.y;
    s[1][cl * 33 + k4 + 2] = v1.z; s[1][cl * 33 + k4 + 3] = v1.w;
    s[2][cl * 33 + k4 + 0] = v2.x; s[2][cl * 33 + k4 + 1] = v2.y;
    s[2][cl * 33 + k4 + 2] = v2.z; s[2][cl * 33 + k4 + 3] = v2.w;
    s[3][cl * 33 + k4 + 0] = v3.x; s[3][cl * 33 + k4 + 1] = v3.y;
    s[3][cl * 33 + k4 + 2] = v3.z; s[3][cl * 33 + k4 + 3] = v3.w;
    __syncthreads();

    // Write: 512 units (4 tiles x 32 nk x 4 c-groups of 8); 2 per thread.
    #pragma unroll
    for (int uu = 0; uu < 2; uu++) {
        const int u   = uu * 256 + tid;
        const int j   = u >> 7;           // sub-tile 0..3
        const int r   = u & 127;
        const int nkl = r >> 2;           // 0..31
        const int c8  = (r & 3) * 8;      // 0..24
        __half2 h0 = __floats2half2_rn(s[j][(c8+0)*33 + nkl], s[j][(c8+1)*33 + nkl]);
        __half2 h1 = __floats2half2_rn(s[j][(c8+2)*33 + nkl], s[j][(c8+3)*33 + nkl]);
        __half2 h2 = __floats2half2_rn(s[j][(c8+4)*33 + nkl], s[j][(c8+5)*33 + nkl]);
        __half2 h3 = __floats2half2_rn(s[j][(c8+6)*33 + nkl], s[j][(c8+7)*33 + nkl]);
        uint4 pk;
        pk.x = *reinterpret_cast<unsigned*>(&h0);
        pk.y = *reinterpret_cast<unsigned*>(&h1);
        pk.z = *reinterpret_cast<unsigned*>(&h2);
        pk.w = *reinterpret_cast<unsigned*>(&h3);
        *reinterpret_cast<uint4*>(&g_wt[(size_t)(nk0 + j * 32 + nkl) * Cc + c0 + c8]) = pk;
    }
}

// ---------------------------------------------------------------------------
// Kernel A2: build combined temporal-edge tables from g_wt.
// ---------------------------------------------------------------------------
__global__ void __launch_bounds__(256) wt_combine_kernel()
{
    const int idx = blockIdx.x * 256 + threadIdx.x;   // over NCLS*9*128
    const int c2  = idx & 127;
    const int jt  = (idx >> 7) % 9;
    const int n   = idx / (9 * 128);

    const __half2* wt2 = reinterpret_cast<const __half2*>(g_wt);
    __half2 h0 = wt2[(n * 27 + jt)      * 128 + c2];
    __half2 h1 = wt2[(n * 27 + 9 + jt)  * 128 + c2];
    __half2 h2 = wt2[(n * 27 + 18 + jt) * 128 + c2];
    float2 f0 = __half22float2(h0), f1 = __half22float2(h1), f2 = __half22float2(h2);
    float sx01 = f0.x + f1.x, sy01 = f0.y + f1.y;
    reinterpret_cast<__half2*>(g_wc01)[(n * 9 + jt) * 128 + c2]  = __floats2half2_rn(sx01, sy01);
    reinterpret_cast<__half2*>(g_wc012)[(n * 9 + jt) * 128 + c2] = __floats2half2_rn(sx01 + f2.x, sy01 + f2.y);
}

// ---------------------------------------------------------------------------
// Kernel B: gather-accumulate — EXACT R11 config (best main: 175.0us).
// LDG.128, pairwise HADD2, fp16 smem staging, full pass unroll @ occ 4,
// temporal-edge combined taps. At the l1tex steady-state service ceiling.
// ---------------------------------------------------------------------------
__global__ void __launch_bounds__(256, 4) onehot_conv_kernel(
    const int*   __restrict__ indices,
    const float* __restrict__ bias,
    float*       __restrict__ out)
{
    __shared__ __align__(16) uint4 s_stage[WCHUNK * 32];  // fp16 stage, 16KB
    __shared__ int s_off[9 * 34];                         // raw classes, halo'd in w

    const int bx   = blockIdx.x;
    const int wblk = bx & 1;
    const int h    = (bx >> 1) & 63;
    const int t    = (bx >> 7) & 15;
    const int b    = bx >> 11;
    const int w0   = wblk * WCHUNK;
    const int tid  = threadIdx.x;

    for (int i = tid; i < 9 * 34; i += 256) {
        int r  = i / 34, j = i % 34;
        int dt = r / 3,  dh = r % 3;
        int st = t + dt - 2; if (st < 0) st = 0;
        int sh = h + dh - 1; if (sh < 0) sh = 0; if (sh > Hh - 1) sh = Hh - 1;
        int gw = w0 + j - 1; if (gw < 0) gw = 0; if (gw > Ww - 1) gw = Ww - 1;
        s_off[i] = indices[((b * Tt + st) * Hh + sh) * Ww + gw];
    }
    __syncthreads();

    const int warp = tid >> 5;
    const int lane = tid & 31;
    const int kl   = lane < 27 ? lane : 26;
    const int rIdx = (kl / 3) * 34 + (kl % 3);

    const char* baseW  = reinterpret_cast<const char*>(g_wt)    + lane * 16;
    const char* baseC1 = reinterpret_cast<const char*>(g_wc01)  + lane * 16;
    const char* baseC2 = reinterpret_cast<const char*>(g_wc012) + lane * 16;

    const float4 bz0 = *reinterpret_cast<const float4*>(bias + 8 * lane);
    const float4 bz1 = *reinterpret_cast<const float4*>(bias + 8 * lane + 4);

    #pragma unroll
    for (int p = 0; p < 4; p++) {
        const int w_l = p * 8 + warp;
        const int cls = s_off[rIdx + w_l];
        const int moW = cls * WOFF_BYTES;
        const int moC = cls * CWOFF_BYTES;

        float4 a0 = bz0, a1 = bz1;

        if (t >= 2) {
            #pragma unroll
            for (int k = 0; k < 26; k += 2) {
                const int o0 = __shfl_sync(0xffffffffu, moW, k);
                const int o1 = __shfl_sync(0xffffffffu, moW, k + 1);
                uint4 u0 = *reinterpret_cast<const uint4*>(baseW + o0 + k * 512);
                uint4 u1 = *reinterpret_cast<const uint4*>(baseW + o1 + (k + 1) * 512);
                __half2 s0 = __hadd2(*reinterpret_cast<__half2*>(&u0.x), *reinterpret_cast<__half2*>(&u1.x));
                __half2 s1 = __hadd2(*reinterpret_cast<__half2*>(&u0.y), *reinterpret_cast<__half2*>(&u1.y));
                __half2 s2 = __hadd2(*reinterpret_cast<__half2*>(&u0.z), *reinterpret_cast<__half2*>(&u1.z));
                __half2 s3 = __hadd2(*reinterpret_cast<__half2*>(&u0.w), *reinterpret_cast<__half2*>(&u1.w));
                float2 f;
                f = __half22float2(s0); a0.x += f.x; a0.y += f.y;
                f = __half22float2(s1); a0.z += f.x; a0.w += f.y;
                f = __half22float2(s2); a1.x += f.x; a1.y += f.y;
                f = __half22float2(s3); a1.z += f.x; a1.w += f.y;
            }
            const int o = __shfl_sync(0xffffffffu, moW, 26);
            uint4 u = *reinterpret_cast<const uint4*>(baseW + o + 26 * 512);
            float2 f;
            f = __half22float2(*reinterpret_cast<__half2*>(&u.x)); a0.x += f.x; a0.y += f.y;
            f = __half22float2(*reinterpret_cast<__half2*>(&u.y)); a0.z += f.x; a0.w += f.y;
            f = __half22float2(*reinterpret_cast<__half2*>(&u.z)); a1.x += f.x; a1.y += f.y;
            f = __half22float2(*reinterpret_cast<__half2*>(&u.w)); a1.z += f.x; a1.w += f.y;
        } else if (t == 1) {
            #pragma unroll
            for (int j = 0; j < 9; j++) {
                const int oc = __shfl_sync(0xffffffffu, moC, j);
                const int ow = __shfl_sync(0xffffffffu, moW, 18 + j);
                uint4 u0 = *reinterpret_cast<const uint4*>(baseC1 + oc + j * 512);
                uint4 u1 = *reinterpret_cast<const uint4*>(baseW + ow + (18 + j) * 512);
                __half2 s0 = __hadd2(*reinterpret_cast<__half2*>(&u0.x), *reinterpret_cast<__half2*>(&u1.x));
                __half2 s1 = __hadd2(*reinterpret_cast<__half2*>(&u0.y), *reinterpret_cast<__half2*>(&u1.y));
                __half2 s2 = __hadd2(*reinterpret_cast<__half2*>(&u0.z), *reinterpret_cast<__half2*>(&u1.z));
                __half2 s3 = __hadd2(*reinterpret_cast<__half2*>(&u0.w), *reinterpret_cast<__half2*>(&u1.w));
                float2 f;
                f = __half22float2(s0); a0.x += f.x; a0.y += f.y;
                f = __half22float2(s1); a0.z += f.x; a0.w += f.y;
                f = __half22float2(s2); a1.x += f.x; a1.y += f.y;
                f = __half22float2(s3); a1.z += f.x; a1.w += f.y;
            }
        } else {
            #pragma unroll
            for (int j = 0; j < 8; j += 2) {
                const int o0 = __shfl_sync(0xffffffffu, moC, j);
                const int o1 = __shfl_sync(0xffffffffu, moC, j + 1);
                uint4 u0 = *reinterpret_cast<const uint4*>(baseC2 + o0 + j * 512);
                uint4 u1 = *reinterpret_cast<const uint4*>(baseC2 + o1 + (j + 1) * 512);
                __half2 s0 = __hadd2(*reinterpret_cast<__half2*>(&u0.x), *reinterpret_cast<__half2*>(&u1.x));
                __half2 s1 = __hadd2(*reinterpret_cast<__half2*>(&u0.y), *reinterpret_cast<__half2*>(&u1.y));
                __half2 s2 = __hadd2(*reinterpret_cast<__half2*>(&u0.z), *reinterpret_cast<__half2*>(&u1.z));
                __half2 s3 = __hadd2(*reinterpret_cast<__half2*>(&u0.w), *reinterpret_cast<__half2*>(&u1.w));
                float2 f;
                f = __half22float2(s0); a0.x += f.x; a0.y += f.y;
                f = __half22float2(s1); a0.z += f.x; a0.w += f.y;
                f = __half22float2(s2); a1.x += f.x; a1.y += f.y;
                f = __half22float2(s3); a1.z += f.x; a1.w += f.y;
            }
            const int o = __shfl_sync(0xffffffffu, moC, 8);
            uint4 u = *reinterpret_cast<const uint4*>(baseC2 + o + 8 * 512);
            float2 f;
            f = __half22float2(*reinterpret_cast<__half2*>(&u.x)); a0.x += f.x; a0.y += f.y;
            f = __half22float2(*reinterpret_cast<__half2*>(&u.y)); a0.z += f.x; a0.w += f.y;
            f = __half22float2(*reinterpret_cast<__half2*>(&u.z)); a1.x += f.x; a1.y += f.y;
            f = __half22float2(*reinterpret_cast<__half2*>(&u.w)); a1.z += f.x; a1.w += f.y;
        }

        __half2 h0 = __floats2half2_rn(a0.x, a0.y);
        __half2 h1 = __floats2half2_rn(a0.z, a0.w);
        __half2 h2 = __floats2half2_rn(a1.x, a1.y);
        __half2 h3 = __floats2half2_rn(a1.z, a1.w);
        uint4 pk;
        pk.x = *reinterpret_cast<unsigned*>(&h0);
        pk.y = *reinterpret_cast<unsigned*>(&h1);
        pk.z = *reinterpret_cast<unsigned*>(&h2);
        pk.w = *reinterpret_cast<unsigned*>(&h3);
        s_stage[w_l * 32 + (lane ^ (w_l & 31))] = pk;
    }
    __syncthreads();

    const size_t THW   = (size_t)Tt * Hh * Ww;
    const size_t obase = (size_t)b * Cc * THW + (size_t)t * (Hh * Ww) + (size_t)h * Ww + w0;
    #pragma unroll
    for (int uu = warp; uu < 32; uu += 8) {
        uint4 pk = s_stage[lane * 32 + (uu ^ lane)];
        float2 f0 = __half22float2(*reinterpret_cast<__half2*>(&pk.x));
        float2 f1 = __half22float2(*reinterpret_cast<__half2*>(&pk.y));
        float2 f2 = __half22float2(*reinterpret_cast<__half2*>(&pk.z));
        float2 f3 = __half22float2(*reinterpret_cast<__half2*>(&pk.w));
        const int c = uu * 8;
        out[obase + (size_t)(c + 0) * THW + lane] = f0.x;
        out[obase + (size_t)(c + 1) * THW + lane] = f0.y;
        out[obase + (size_t)(c + 2) * THW + lane] = f1.x;
        out[obase + (size_t)(c + 3) * THW + lane] = f1.y;
        out[obase + (size_t)(c + 4) * THW + lane] = f2.x;
        out[obase + (size_t)(c + 5) * THW + lane] = f2.y;
        out[obase + (size_t)(c + 6) * THW + lane] = f3.x;
        out[obase + (size_t)(c + 7) * THW + lane] = f3.y;
    }
}

// ---------------------------------------------------------------------------
extern "C" void kernel_launch(void* const* d_in, const int* in_sizes, int n_in,
                              void* d_out, int out_size)
{
    const int*   indices = (const int*)  d_in[0];
    const float* weight  = (const float*)d_in[1];
    const float* bias    = (const float*)d_in[2];
    float*       out     = (float*)d_out;

    dim3 tgrid(NK / 128, Cc / 32);                 // (108, 8)
    wt_transpose_kernel<<<tgrid, 256>>>(weight);
    wt_combine_kernel<<<NCLS * 9 * 128 / 256, 256>>>();

    const int grid = Bb * Tt * Hh * (Ww / WCHUNK); // 8192
    onehot_conv_kernel<<<grid, 256>>>(indices, bias, out);
}

// round 16
// speedup vs baseline: 1.0274x; 1.0072x over previous
#include <cuda_runtime.h>
#include <cuda_fp16.h>

// Problem constants
#define Bb    4
#define Tt    16
#define Hh    64
#define Ww    64
#define Cc    256
#define NCLS  512
#define TAPS  27
#define NK    (NCLS * TAPS)           // 13824
#define WCHUNK 32
#define WOFF_BYTES  (TAPS * Cc * 2)   // 13824 B per class in main table
#define CWOFF_BYTES (9 * Cc * 2)      // 4608 B per class in combined tables

// Transposed fp16 weight table: [class][tap][channel]
__device__ __align__(16) __half g_wt[NK * Cc];
// Temporal-edge combined tables: [class][dh*3+dw][channel]
__device__ __align__(16) __half g_wc01 [NCLS * 9 * Cc];
__device__ __align__(16) __half g_wc012[NCLS * 9 * Cc];

// ---------------------------------------------------------------------------
// Kernel A (merged): transpose + fp16 convert + combined edge tables in ONE
// kernel. Block = 4 whole classes x 32 channels (108 nk rows), so the smem
// tile holds all 27 taps of its classes in fp32 and can emit g_wt AND the
// combined tables (fp32 sums, single fp16 rounding — better precision than
// R11's combine-from-fp16). Eliminates the combine kernel's launch + its
// 11.8MB g_wt re-read. grid = (NCLS/4, Cc/32) = (128, 8).
// ---------------------------------------------------------------------------
#define SPAD 109   // smem row stride (108 + 1)

__global__ void __launch_bounds__(256) wt_prep_kernel(const float* __restrict__ w)
{
    __shared__ float s[32 * SPAD];      // [c_local][nk_local 0..107]
    const int n0  = blockIdx.x * 4;     // first class of group
    const int c0  = blockIdx.y * 32;
    const int tid = threadIdx.x;

    // Load: 864 float4 units (32 c-rows x 27 float4). ~3.4 independent
    // LDG.128 per thread.
    for (int i = tid; i < 32 * 27; i += 256) {
        const int cl = i / 27;
        const int f4 = i % 27;
        float4 v = *reinterpret_cast<const float4*>(
            w + (size_t)(c0 + cl) * NK + n0 * TAPS + f4 * 4);
        s[cl * SPAD + f4 * 4 + 0] = v.x;
        s[cl * SPAD + f4 * 4 + 1] = v.y;
        s[cl * SPAD + f4 * 4 + 2] = v.z;
        s[cl * SPAD + f4 * 4 + 3] = v.w;
    }
    __syncthreads();

    // Write g_wt: 432 units (108 nk x 4 c-groups of 8) -> STG.128 each.
    for (int u = tid; u < 108 * 4; u += 256) {
        const int nkl = u >> 2;           // 0..107
        const int c8  = (u & 3) * 8;      // 0..24
        __half2 h0 = __floats2half2_rn(s[(c8+0)*SPAD + nkl], s[(c8+1)*SPAD + nkl]);
        __half2 h1 = __floats2half2_rn(s[(c8+2)*SPAD + nkl], s[(c8+3)*SPAD + nkl]);
        __half2 h2 = __floats2half2_rn(s[(c8+4)*SPAD + nkl], s[(c8+5)*SPAD + nkl]);
        __half2 h3 = __floats2half2_rn(s[(c8+6)*SPAD + nkl], s[(c8+7)*SPAD + nkl]);
        uint4 pk;
        pk.x = *reinterpret_cast<unsigned*>(&h0);
        pk.y = *reinterpret_cast<unsigned*>(&h1);
        pk.z = *reinterpret_cast<unsigned*>(&h2);
        pk.w = *reinterpret_cast<unsigned*>(&h3);
        *reinterpret_cast<uint4*>(&g_wt[(size_t)(n0 * TAPS + nkl) * Cc + c0 + c8]) = pk;
    }

    // Write combined tables: 144 units (4 classes x 9 jt x 4 c-groups).
    for (int u = tid; u < 4 * 9 * 4; u += 256) {
        const int g   = u / 36;           // local class 0..3
        const int jt  = (u / 4) % 9;      // dh*3+dw
        const int c8  = (u & 3) * 8;
        const int kb  = g * TAPS + jt;    // nk_local of dt=0 tap
        float v01[8], v012[8];
        #pragma unroll
        for (int e = 0; e < 8; e++) {
            float w0 = s[(c8+e)*SPAD + kb];
            float w1 = s[(c8+e)*SPAD + kb + 9];
            float w2 = s[(c8+e)*SPAD + kb + 18];
            v01[e]  = w0 + w1;
            v012[e] = w0 + w1 + w2;
        }
        uint4 p1, p2; __half2 a;
        a = __floats2half2_rn(v01[0],  v01[1]);  p1.x = *reinterpret_cast<unsigned*>(&a);
        a = __floats2half2_rn(v01[2],  v01[3]);  p1.y = *reinterpret_cast<unsigned*>(&a);
        a = __floats2half2_rn(v01[4],  v01[5]);  p1.z = *reinterpret_cast<unsigned*>(&a);
        a = __floats2half2_rn(v01[6],  v01[7]);  p1.w = *reinterpret_cast<unsigned*>(&a);
        a = __floats2half2_rn(v012[0], v012[1]); p2.x = *reinterpret_cast<unsigned*>(&a);
        a = __floats2half2_rn(v012[2], v012[3]); p2.y = *reinterpret_cast<unsigned*>(&a);
        a = __floats2half2_rn(v012[4], v012[5]); p2.z = *reinterpret_cast<unsigned*>(&a);
        a = __floats2half2_rn(v012[6], v012[7]); p2.w = *reinterpret_cast<unsigned*>(&a);
        const size_t co = (size_t)((n0 + g) * 9 + jt) * Cc + c0 + c8;
        *reinterpret_cast<uint4*>(&g_wc01 [co]) = p1;
        *reinterpret_cast<uint4*>(&g_wc012[co]) = p2;
    }
}

// ---------------------------------------------------------------------------
// Kernel B: gather-accumulate — EXACT R11 config (best main: 175.0us).
// LDG.128, pairwise HADD2, fp16 smem staging, full pass unroll @ occ 4,
// temporal-edge combined taps. At the l1tex steady-state service ceiling.
// ---------------------------------------------------------------------------
__global__ void __launch_bounds__(256, 4) onehot_conv_kernel(
    const int*   __restrict__ indices,
    const float* __restrict__ bias,
    float*       __restrict__ out)
{
    __shared__ __align__(16) uint4 s_stage[WCHUNK * 32];  // fp16 stage, 16KB
    __shared__ int s_off[9 * 34];                         // raw classes, halo'd in w

    const int bx   = blockIdx.x;
    const int wblk = bx & 1;
    const int h    = (bx >> 1) & 63;
    const int t    = (bx >> 7) & 15;
    const int b    = bx >> 11;
    const int w0   = wblk * WCHUNK;
    const int tid  = threadIdx.x;

    for (int i = tid; i < 9 * 34; i += 256) {
        int r  = i / 34, j = i % 34;
        int dt = r / 3,  dh = r % 3;
        int st = t + dt - 2; if (st < 0) st = 0;
        int sh = h + dh - 1; if (sh < 0) sh = 0; if (sh > Hh - 1) sh = Hh - 1;
        int gw = w0 + j - 1; if (gw < 0) gw = 0; if (gw > Ww - 1) gw = Ww - 1;
        s_off[i] = indices[((b * Tt + st) * Hh + sh) * Ww + gw];
    }
    __syncthreads();

    const int warp = tid >> 5;
    const int lane = tid & 31;
    const int kl   = lane < 27 ? lane : 26;
    const int rIdx = (kl / 3) * 34 + (kl % 3);

    const char* baseW  = reinterpret_cast<const char*>(g_wt)    + lane * 16;
    const char* baseC1 = reinterpret_cast<const char*>(g_wc01)  + lane * 16;
    const char* baseC2 = reinterpret_cast<const char*>(g_wc012) + lane * 16;

    const float4 bz0 = *reinterpret_cast<const float4*>(bias + 8 * lane);
    const float4 bz1 = *reinterpret_cast<const float4*>(bias + 8 * lane + 4);

    #pragma unroll
    for (int p = 0; p < 4; p++) {
        const int w_l = p * 8 + warp;
        const int cls = s_off[rIdx + w_l];
        const int moW = cls * WOFF_BYTES;
        const int moC = cls * CWOFF_BYTES;

        float4 a0 = bz0, a1 = bz1;

        if (t >= 2) {
            #pragma unroll
            for (int k = 0; k < 26; k += 2) {
                const int o0 = __shfl_sync(0xffffffffu, moW, k);
                const int o1 = __shfl_sync(0xffffffffu, moW, k + 1);
                uint4 u0 = *reinterpret_cast<const uint4*>(baseW + o0 + k * 512);
                uint4 u1 = *reinterpret_cast<const uint4*>(baseW + o1 + (k + 1) * 512);
                __half2 s0 = __hadd2(*reinterpret_cast<__half2*>(&u0.x), *reinterpret_cast<__half2*>(&u1.x));
                __half2 s1 = __hadd2(*reinterpret_cast<__half2*>(&u0.y), *reinterpret_cast<__half2*>(&u1.y));
                __half2 s2 = __hadd2(*reinterpret_cast<__half2*>(&u0.z), *reinterpret_cast<__half2*>(&u1.z));
                __half2 s3 = __hadd2(*reinterpret_cast<__half2*>(&u0.w), *reinterpret_cast<__half2*>(&u1.w));
                float2 f;
                f = __half22float2(s0); a0.x += f.x; a0.y += f.y;
                f = __half22float2(s1); a0.z += f.x; a0.w += f.y;
                f = __half22float2(s2); a1.x += f.x; a1.y += f.y;
                f = __half22float2(s3); a1.z += f.x; a1.w += f.y;
            }
            const int o = __shfl_sync(0xffffffffu, moW, 26);
            uint4 u = *reinterpret_cast<const uint4*>(baseW + o + 26 * 512);
            float2 f;
            f = __half22float2(*reinterpret_cast<__half2*>(&u.x)); a0.x += f.x; a0.y += f.y;
            f = __half22float2(*reinterpret_cast<__half2*>(&u.y)); a0.z += f.x; a0.w += f.y;
            f = __half22float2(*reinterpret_cast<__half2*>(&u.z)); a1.x += f.x; a1.y += f.y;
            f = __half22float2(*reinterpret_cast<__half2*>(&u.w)); a1.z += f.x; a1.w += f.y;
        } else if (t == 1) {
            #pragma unroll
            for (int j = 0; j < 9; j++) {
                const int oc = __shfl_sync(0xffffffffu, moC, j);
                const int ow = __shfl_sync(0xffffffffu, moW, 18 + j);
                uint4 u0 = *reinterpret_cast<const uint4*>(baseC1 + oc + j * 512);
                uint4 u1 = *reinterpret_cast<const uint4*>(baseW + ow + (18 + j) * 512);
                __half2 s0 = __hadd2(*reinterpret_cast<__half2*>(&u0.x), *reinterpret_cast<__half2*>(&u1.x));
                __half2 s1 = __hadd2(*reinterpret_cast<__half2*>(&u0.y), *reinterpret_cast<__half2*>(&u1.y));
                __half2 s2 = __hadd2(*reinterpret_cast<__half2*>(&u0.z), *reinterpret_cast<__half2*>(&u1.z));
                __half2 s3 = __hadd2(*reinterpret_cast<__half2*>(&u0.w), *reinterpret_cast<__half2*>(&u1.w));
                float2 f;
                f = __half22float2(s0); a0.x += f.x; a0.y += f.y;
                f = __half22float2(s1); a0.z += f.x; a0.w += f.y;
                f = __half22float2(s2); a1.x += f.x; a1.y += f.y;
                f = __half22float2(s3); a1.z += f.x; a1.w += f.y;
            }
        } else {
            #pragma unroll
            for (int j = 0; j < 8; j += 2) {
                const int o0 = __shfl_sync(0xffffffffu, moC, j);
                const int o1 = __shfl_sync(0xffffffffu, moC, j + 1);
                uint4 u0 = *reinterpret_cast<const uint4*>(baseC2 + o0 + j * 512);
                uint4 u1 = *reinterpret_cast<const uint4*>(baseC2 + o1 + (j + 1) * 512);
                __half2 s0 = __hadd2(*reinterpret_cast<__half2*>(&u0.x), *reinterpret_cast<__half2*>(&u1.x));
                __half2 s1 = __hadd2(*reinterpret_cast<__half2*>(&u0.y), *reinterpret_cast<__half2*>(&u1.y));
                __half2 s2 = __hadd2(*reinterpret_cast<__half2*>(&u0.z), *reinterpret_cast<__half2*>(&u1.z));
                __half2 s3 = __hadd2(*reinterpret_cast<__half2*>(&u0.w), *reinterpret_cast<__half2*>(&u1.w));
                float2 f;
                f = __half22float2(s0); a0.x += f.x; a0.y += f.y;
                f = __half22float2(s1); a0.z += f.x; a0.w += f.y;
                f = __half22float2(s2); a1.x += f.x; a1.y += f.y;
                f = __half22float2(s3); a1.z += f.x; a1.w += f.y;
            }
            const int o = __shfl_sync(0xffffffffu, moC, 8);
            uint4 u = *reinterpret_cast<const uint4*>(baseC2 + o + 8 * 512);
            float2 f;
            f = __half22float2(*reinterpret_cast<__half2*>(&u.x)); a0.x += f.x; a0.y += f.y;
            f = __half22float2(*reinterpret_cast<__half2*>(&u.y)); a0.z += f.x; a0.w += f.y;
            f = __half22float2(*reinterpret_cast<__half2*>(&u.z)); a1.x += f.x; a1.y += f.y;
            f = __half22float2(*reinterpret_cast<__half2*>(&u.w)); a1.z += f.x; a1.w += f.y;
        }

        __half2 h0 = __floats2half2_rn(a0.x, a0.y);
        __half2 h1 = __floats2half2_rn(a0.z, a0.w);
        __half2 h2 = __floats2half2_rn(a1.x, a1.y);
        __half2 h3 = __floats2half2_rn(a1.z, a1.w);
        uint4 pk;
        pk.x = *reinterpret_cast<unsigned*>(&h0);
        pk.y = *reinterpret_cast<unsigned*>(&h1);
        pk.z = *reinterpret_cast<unsigned*>(&h2);
        pk.w = *reinterpret_cast<unsigned*>(&h3);
        s_stage[w_l * 32 + (lane ^ (w_l & 31))] = pk;
    }
    __syncthreads();

    const size_t THW   = (size_t)Tt * Hh * Ww;
    const size_t obase = (size_t)b * Cc * THW + (size_t)t * (Hh * Ww) + (size_t)h * Ww + w0;
    #pragma unroll
    for (int uu = warp; uu < 32; uu += 8) {
        uint4 pk = s_stage[lane * 32 + (uu ^ lane)];
        float2 f0 = __half22float2(*reinterpret_cast<__half2*>(&pk.x));
        float2 f1 = __half22float2(*reinterpret_cast<__half2*>(&pk.y));
        float2 f2 = __half22float2(*reinterpret_cast<__half2*>(&pk.z));
        float2 f3 = __half22float2(*reinterpret_cast<__half2*>(&pk.w));
        const int c = uu * 8;
        out[obase + (size_t)(c + 0) * THW + lane] = f0.x;
        out[obase + (size_t)(c + 1) * THW + lane] = f0.y;
        out[obase + (size_t)(c + 2) * THW + lane] = f1.x;
        out[obase + (size_t)(c + 3) * THW + lane] = f1.y;
        out[obase + (size_t)(c + 4) * THW + lane] = f2.x;
        out[obase + (size_t)(c + 5) * THW + lane] = f2.y;
        out[obase + (size_t)(c + 6) * THW + lane] = f3.x;
        out[obase + (size_t)(c + 7) * THW + lane] = f3.y;
    }
}

// ---------------------------------------------------------------------------
extern "C" void kernel_launch(void* const* d_in, const int* in_sizes, int n_in,
                              void* d_out, int out_size)
{
    const int*   indices = (const int*)  d_in[0];
    const float* weight  = (const float*)d_in[1];
    const float* bias    = (const float*)d_in[2];
    float*       out     = (float*)d_out;

    dim3 pgrid(NCLS / 4, Cc / 32);                 // (128, 8)
    wt_prep_kernel<<<pgrid, 256>>>(weight);

    const int grid = Bb * Tt * Hh * (Ww / WCHUNK); // 8192
    onehot_conv_kernel<<<grid, 256>>>(indices, bias, out);
}

// round 17
// speedup vs baseline: 1.0357x; 1.0081x over previous
#include <cuda_runtime.h>
#include <cuda_fp16.h>

// Problem constants
#define Bb    4
#define Tt    16
#define Hh    64
#define Ww    64
#define Cc    256
#define NCLS  512
#define TAPS  27
#define NK    (NCLS * TAPS)           // 13824
#define WCHUNK 32
#define WOFF_BYTES  (TAPS * Cc * 2)   // 13824 B per class in main table
#define CWOFF_BYTES (9 * Cc * 2)      // 4608 B per class in combined tables

// Transposed fp16 weight table: [class][tap][channel]
__device__ __align__(16) __half g_wt[NK * Cc];
// Temporal-edge combined tables: [class][dh*3+dw][channel]
__device__ __align__(16) __half g_wc01 [NCLS * 9 * Cc];
__device__ __align__(16) __half g_wc012[NCLS * 9 * Cc];

// ---------------------------------------------------------------------------
// Kernel A (merged prep, R16): transpose + fp16 convert + combined edge
// tables. R17: issues griddepcontrol.launch_dependents at entry so the PDL
// secondary (main kernel) can begin its table-independent phase immediately.
// ---------------------------------------------------------------------------
#define SPAD 109   // smem row stride (108 + 1)

__global__ void __launch_bounds__(256) wt_prep_kernel(const float* __restrict__ w)
{
    asm volatile("griddepcontrol.launch_dependents;");

    __shared__ float s[32 * SPAD];      // [c_local][nk_local 0..107]
    const int n0  = blockIdx.x * 4;     // first class of group
    const int c0  = blockIdx.y * 32;
    const int tid = threadIdx.x;

    for (int i = tid; i < 32 * 27; i += 256) {
        const int cl = i / 27;
        const int f4 = i % 27;
        float4 v = *reinterpret_cast<const float4*>(
            w + (size_t)(c0 + cl) * NK + n0 * TAPS + f4 * 4);
        s[cl * SPAD + f4 * 4 + 0] = v.x;
        s[cl * SPAD + f4 * 4 + 1] = v.y;
        s[cl * SPAD + f4 * 4 + 2] = v.z;
        s[cl * SPAD + f4 * 4 + 3] = v.w;
    }
    __syncthreads();

    // g_wt: 432 units (108 nk x 4 c-groups of 8) -> STG.128 each.
    for (int u = tid; u < 108 * 4; u += 256) {
        const int nkl = u >> 2;
        const int c8  = (u & 3) * 8;
        __half2 h0 = __floats2half2_rn(s[(c8+0)*SPAD + nkl], s[(c8+1)*SPAD + nkl]);
        __half2 h1 = __floats2half2_rn(s[(c8+2)*SPAD + nkl], s[(c8+3)*SPAD + nkl]);
        __half2 h2 = __floats2half2_rn(s[(c8+4)*SPAD + nkl], s[(c8+5)*SPAD + nkl]);
        __half2 h3 = __floats2half2_rn(s[(c8+6)*SPAD + nkl], s[(c8+7)*SPAD + nkl]);
        uint4 pk;
        pk.x = *reinterpret_cast<unsigned*>(&h0);
        pk.y = *reinterpret_cast<unsigned*>(&h1);
        pk.z = *reinterpret_cast<unsigned*>(&h2);
        pk.w = *reinterpret_cast<unsigned*>(&h3);
        *reinterpret_cast<uint4*>(&g_wt[(size_t)(n0 * TAPS + nkl) * Cc + c0 + c8]) = pk;
    }

    // Combined tables: 144 units (4 classes x 9 jt x 4 c-groups).
    for (int u = tid; u < 4 * 9 * 4; u += 256) {
        const int g   = u / 36;
        const int jt  = (u / 4) % 9;
        const int c8  = (u & 3) * 8;
        const int kb  = g * TAPS + jt;
        float v01[8], v012[8];
        #pragma unroll
        for (int e = 0; e < 8; e++) {
            float w0 = s[(c8+e)*SPAD + kb];
            float w1 = s[(c8+e)*SPAD + kb + 9];
            float w2 = s[(c8+e)*SPAD + kb + 18];
            v01[e]  = w0 + w1;
            v012[e] = w0 + w1 + w2;
        }
        uint4 p1, p2; __half2 a;
        a = __floats2half2_rn(v01[0],  v01[1]);  p1.x = *reinterpret_cast<unsigned*>(&a);
        a = __floats2half2_rn(v01[2],  v01[3]);  p1.y = *reinterpret_cast<unsigned*>(&a);
        a = __floats2half2_rn(v01[4],  v01[5]);  p1.z = *reinterpret_cast<unsigned*>(&a);
        a = __floats2half2_rn(v01[6],  v01[7]);  p1.w = *reinterpret_cast<unsigned*>(&a);
        a = __floats2half2_rn(v012[0], v012[1]); p2.x = *reinterpret_cast<unsigned*>(&a);
        a = __floats2half2_rn(v012[2], v012[3]); p2.y = *reinterpret_cast<unsigned*>(&a);
        a = __floats2half2_rn(v012[4], v012[5]); p2.z = *reinterpret_cast<unsigned*>(&a);
        a = __floats2half2_rn(v012[6], v012[7]); p2.w = *reinterpret_cast<unsigned*>(&a);
        const size_t co = (size_t)((n0 + g) * 9 + jt) * Cc + c0 + c8;
        *reinterpret_cast<uint4*>(&g_wc01 [co]) = p1;
        *reinterpret_cast<uint4*>(&g_wc012[co]) = p2;
    }
}

// ---------------------------------------------------------------------------
// Kernel B: gather-accumulate — R16 config (main 173.4us, at its l1tex
// service ceiling). R17: PDL secondary — halo/bias phase runs before
// griddepcontrol.wait; first weight-table access is after the wait.
// ---------------------------------------------------------------------------
__global__ void __launch_bounds__(256, 4) onehot_conv_kernel(
    const int*   __restrict__ indices,
    const float* __restrict__ bias,
    float*       __restrict__ out)
{
    __shared__ __align__(16) uint4 s_stage[WCHUNK * 32];  // fp16 stage, 16KB
    __shared__ int s_off[9 * 34];                         // raw classes, halo'd in w

    const int bx   = blockIdx.x;
    const int wblk = bx & 1;
    const int h    = (bx >> 1) & 63;
    const int t    = (bx >> 7) & 15;
    const int b    = bx >> 11;
    const int w0   = wblk * WCHUNK;
    const int tid  = threadIdx.x;

    // Phase 1 (independent of prep): index halo + bias loads.
    for (int i = tid; i < 9 * 34; i += 256) {
        int r  = i / 34, j = i % 34;
        int dt = r / 3,  dh = r % 3;
        int st = t + dt - 2; if (st < 0) st = 0;
        int sh = h + dh - 1; if (sh < 0) sh = 0; if (sh > Hh - 1) sh = Hh - 1;
        int gw = w0 + j - 1; if (gw < 0) gw = 0; if (gw > Ww - 1) gw = Ww - 1;
        s_off[i] = indices[((b * Tt + st) * Hh + sh) * Ww + gw];
    }
    __syncthreads();

    const int warp = tid >> 5;
    const int lane = tid & 31;
    const int kl   = lane < 27 ? lane : 26;
    const int rIdx = (kl / 3) * 34 + (kl % 3);

    const char* baseW  = reinterpret_cast<const char*>(g_wt)    + lane * 16;
    const char* baseC1 = reinterpret_cast<const char*>(g_wc01)  + lane * 16;
    const char* baseC2 = reinterpret_cast<const char*>(g_wc012) + lane * 16;

    const float4 bz0 = *reinterpret_cast<const float4*>(bias + 8 * lane);
    const float4 bz1 = *reinterpret_cast<const float4*>(bias + 8 * lane + 4);

    // Phase 2: weight tables — wait for prep completion first.
    asm volatile("griddepcontrol.wait;" ::: "memory");

    #pragma unroll
    for (int p = 0; p < 4; p++) {
        const int w_l = p * 8 + warp;
        const int cls = s_off[rIdx + w_l];
        const int moW = cls * WOFF_BYTES;
        const int moC = cls * CWOFF_BYTES;

        float4 a0 = bz0, a1 = bz1;

        if (t >= 2) {
            #pragma unroll
            for (int k = 0; k < 26; k += 2) {
                const int o0 = __shfl_sync(0xffffffffu, moW, k);
                const int o1 = __shfl_sync(0xffffffffu, moW, k + 1);
                uint4 u0 = *reinterpret_cast<const uint4*>(baseW + o0 + k * 512);
                uint4 u1 = *reinterpret_cast<const uint4*>(baseW + o1 + (k + 1) * 512);
                __half2 s0 = __hadd2(*reinterpret_cast<__half2*>(&u0.x), *reinterpret_cast<__half2*>(&u1.x));
                __half2 s1 = __hadd2(*reinterpret_cast<__half2*>(&u0.y), *reinterpret_cast<__half2*>(&u1.y));
                __half2 s2 = __hadd2(*reinterpret_cast<__half2*>(&u0.z), *reinterpret_cast<__half2*>(&u1.z));
                __half2 s3 = __hadd2(*reinterpret_cast<__half2*>(&u0.w), *reinterpret_cast<__half2*>(&u1.w));
                float2 f;
                f = __half22float2(s0); a0.x += f.x; a0.y += f.y;
                f = __half22float2(s1); a0.z += f.x; a0.w += f.y;
                f = __half22float2(s2); a1.x += f.x; a1.y += f.y;
                f = __half22float2(s3); a1.z += f.x; a1.w += f.y;
            }
            const int o = __shfl_sync(0xffffffffu, moW, 26);
            uint4 u = *reinterpret_cast<const uint4*>(baseW + o + 26 * 512);
            float2 f;
            f = __half22float2(*reinterpret_cast<__half2*>(&u.x)); a0.x += f.x; a0.y += f.y;
            f = __half22float2(*reinterpret_cast<__half2*>(&u.y)); a0.z += f.x; a0.w += f.y;
            f = __half22float2(*reinterpret_cast<__half2*>(&u.z)); a1.x += f.x; a1.y += f.y;
            f = __half22float2(*reinterpret_cast<__half2*>(&u.w)); a1.z += f.x; a1.w += f.y;
        } else if (t == 1) {
            #pragma unroll
            for (int j = 0; j < 9; j++) {
                const int oc = __shfl_sync(0xffffffffu, moC, j);
                const int ow = __shfl_sync(0xffffffffu, moW, 18 + j);
                uint4 u0 = *reinterpret_cast<const uint4*>(baseC1 + oc + j * 512);
                uint4 u1 = *reinterpret_cast<const uint4*>(baseW + ow + (18 + j) * 512);
                __half2 s0 = __hadd2(*reinterpret_cast<__half2*>(&u0.x), *reinterpret_cast<__half2*>(&u1.x));
                __half2 s1 = __hadd2(*reinterpret_cast<__half2*>(&u0.y), *reinterpret_cast<__half2*>(&u1.y));
                __half2 s2 = __hadd2(*reinterpret_cast<__half2*>(&u0.z), *reinterpret_cast<__half2*>(&u1.z));
                __half2 s3 = __hadd2(*reinterpret_cast<__half2*>(&u0.w), *reinterpret_cast<__half2*>(&u1.w));
                float2 f;
                f = __half22float2(s0); a0.x += f.x; a0.y += f.y;
                f = __half22float2(s1); a0.z += f.x; a0.w += f.y;
                f = __half22float2(s2); a1.x += f.x; a1.y += f.y;
                f = __half22float2(s3); a1.z += f.x; a1.w += f.y;
            }
        } else {
            #pragma unroll
            for (int j = 0; j < 8; j += 2) {
                const int o0 = __shfl_sync(0xffffffffu, moC, j);
                const int o1 = __shfl_sync(0xffffffffu, moC, j + 1);
                uint4 u0 = *reinterpret_cast<const uint4*>(baseC2 + o0 + j * 512);
                uint4 u1 = *reinterpret_cast<const uint4*>(baseC2 + o1 + (j + 1) * 512);
                __half2 s0 = __hadd2(*reinterpret_cast<__half2*>(&u0.x), *reinterpret_cast<__half2*>(&u1.x));
                __half2 s1 = __hadd2(*reinterpret_cast<__half2*>(&u0.y), *reinterpret_cast<__half2*>(&u1.y));
                __half2 s2 = __hadd2(*reinterpret_cast<__half2*>(&u0.z), *reinterpret_cast<__half2*>(&u1.z));
                __half2 s3 = __hadd2(*reinterpret_cast<__half2*>(&u0.w), *reinterpret_cast<__half2*>(&u1.w));
                float2 f;
                f = __half22float2(s0); a0.x += f.x; a0.y += f.y;
                f = __half22float2(s1); a0.z += f.x; a0.w += f.y;
                f = __half22float2(s2); a1.x += f.x; a1.y += f.y;
                f = __half22float2(s3); a1.z += f.x; a1.w += f.y;
            }
            const int o = __shfl_sync(0xffffffffu, moC, 8);
            uint4 u = *reinterpret_cast<const uint4*>(baseC2 + o + 8 * 512);
            float2 f;
            f = __half22float2(*reinterpret_cast<__half2*>(&u.x)); a0.x += f.x; a0.y += f.y;
            f = __half22float2(*reinterpret_cast<__half2*>(&u.y)); a0.z += f.x; a0.w += f.y;
            f = __half22float2(*reinterpret_cast<__half2*>(&u.z)); a1.x += f.x; a1.y += f.y;
            f = __half22float2(*reinterpret_cast<__half2*>(&u.w)); a1.z += f.x; a1.w += f.y;
        }

        __half2 h0 = __floats2half2_rn(a0.x, a0.y);
        __half2 h1 = __floats2half2_rn(a0.z, a0.w);
        __half2 h2 = __floats2half2_rn(a1.x, a1.y);
        __half2 h3 = __floats2half2_rn(a1.z, a1.w);
        uint4 pk;
        pk.x = *reinterpret_cast<unsigned*>(&h0);
        pk.y = *reinterpret_cast<unsigned*>(&h1);
        pk.z = *reinterpret_cast<unsigned*>(&h2);
        pk.w = *reinterpret_cast<unsigned*>(&h3);
        s_stage[w_l * 32 + (lane ^ (w_l & 31))] = pk;
    }
    __syncthreads();

    const size_t THW   = (size_t)Tt * Hh * Ww;
    const size_t obase = (size_t)b * Cc * THW + (size_t)t * (Hh * Ww) + (size_t)h * Ww + w0;
    #pragma unroll
    for (int uu = warp; uu < 32; uu += 8) {
        uint4 pk = s_stage[lane * 32 + (uu ^ lane)];
        float2 f0 = __half22float2(*reinterpret_cast<__half2*>(&pk.x));
        float2 f1 = __half22float2(*reinterpret_cast<__half2*>(&pk.y));
        float2 f2 = __half22float2(*reinterpret_cast<__half2*>(&pk.z));
        float2 f3 = __half22float2(*reinterpret_cast<__half2*>(&pk.w));
        const int c = uu * 8;
        out[obase + (size_t)(c + 0) * THW + lane] = f0.x;
        out[obase + (size_t)(c + 1) * THW + lane] = f0.y;
        out[obase + (size_t)(c + 2) * THW + lane] = f1.x;
        out[obase + (size_t)(c + 3) * THW + lane] = f1.y;
        out[obase + (size_t)(c + 4) * THW + lane] = f2.x;
        out[obase + (size_t)(c + 5) * THW + lane] = f2.y;
        out[obase + (size_t)(c + 6) * THW + lane] = f3.x;
        out[obase + (size_t)(c + 7) * THW + lane] = f3.y;
    }
}

// ---------------------------------------------------------------------------
extern "C" void kernel_launch(void* const* d_in, const int* in_sizes, int n_in,
                              void* d_out, int out_size)
{
    const int*   indices = (const int*)  d_in[0];
    const float* weight  = (const float*)d_in[1];
    const float* bias    = (const float*)d_in[2];
    float*       out     = (float*)d_out;

    dim3 pgrid(NCLS / 4, Cc / 32);                 // (128, 8)
    wt_prep_kernel<<<pgrid, 256>>>(weight);

    // Main kernel as PDL secondary: launches while prep runs; table reads
    // are gated by griddepcontrol.wait inside the kernel.
    cudaLaunchConfig_t cfg = {};
    cfg.gridDim  = dim3(Bb * Tt * Hh * (Ww / WCHUNK));  // 8192
    cfg.blockDim = dim3(256);
    cfg.dynamicSmemBytes = 0;
    cfg.stream = 0;
    cudaLaunchAttribute attrs[1];
    attrs[0].id = cudaLaunchAttributeProgrammaticStreamSerialization;
    attrs[0].val.programmaticStreamSerializationAllowed = 1;
    cfg.attrs = attrs;
    cfg.numAttrs = 1;
    cudaLaunchKernelEx(&cfg, onehot_conv_kernel, indices, bias, out);
}